// round 7
// baseline (speedup 1.0000x reference)
#include <cuda_runtime.h>
#include <mma.h>
#include <cstdint>
#include <math.h>

using namespace nvcuda;

#define Bsz   64
#define Hh    2048
#define G4    8192
#define INs   1024
#define Tt    128
#define STAGES 4
#define BK    64
#define LDA   68               // 64 floats + 4 pad
#define LDG   36               // epilogue: 32 cols + 4 pad
#define NLSTM 256
#define NREC  32

#define A_STAGE_FLOATS (64*LDA)            // 4352
#define B_STAGE_FLOATS (32*LDA)            // 2176
#define STAGE_FLOATS   (A_STAGE_FLOATS + B_STAGE_FLOATS)   // 6528 -> 26112 B
#define BSUM_OFF       (STAGES*STAGE_FLOATS)               // 26112 floats
#define SMEM_BYTES     ((BSUM_OFF + 32)*4)                 // 104576 B

// ---- persistent device scratch ----
__device__ float g_Wih[2L*G4*Hh];
__device__ float g_Whh[2L*G4*Hh];
__device__ float g_Wrec[(long)INs*Hh];
__device__ float g_h[4L*Bsz*Hh];
__device__ float g_c[2L*Bsz*Hh];
__device__ float g_x0[(long)Bsz*Hh];

__device__ __forceinline__ float tf32r(float x){
  uint32_t r; asm("cvt.rna.tf32.f32 %0, %1;" : "=r"(r) : "f"(x));
  return __uint_as_float(r);
}
__device__ __forceinline__ uint32_t saddr(const void* p){
  return (uint32_t)__cvta_generic_to_shared(p);
}
__device__ __forceinline__ void cpa16(uint32_t d, const void* s){
  asm volatile("cp.async.cg.shared.global [%0], [%1], 16;" :: "r"(d), "l"(s));
}
__device__ __forceinline__ float sigf(float x){ return 1.f/(1.f+expf(-x)); }

// ---- init: round weights/state to tf32 (rna) ----
__global__ void init_kernel(const float* __restrict__ h0, const float* __restrict__ c0,
                            const float* __restrict__ Wih, const float* __restrict__ Whh,
                            const float* __restrict__ Wrec)
{
  long tid = (long)blockIdx.x*blockDim.x + threadIdx.x;
  long stride = (long)gridDim.x*blockDim.x;

  const long NW = (2L*G4*Hh)/4;
  const float4* s1 = (const float4*)Wih; float4* d1 = (float4*)g_Wih;
  const float4* s2 = (const float4*)Whh; float4* d2 = (float4*)g_Whh;
  for (long i=tid;i<NW;i+=stride){
    float4 v=s1[i]; v.x=tf32r(v.x); v.y=tf32r(v.y); v.z=tf32r(v.z); v.w=tf32r(v.w); d1[i]=v;
    float4 u=s2[i]; u.x=tf32r(u.x); u.y=tf32r(u.y); u.z=tf32r(u.z); u.w=tf32r(u.w); d2[i]=u;
  }
  const long NR = ((long)INs*Hh)/4;
  const float4* s3 = (const float4*)Wrec; float4* d3 = (float4*)g_Wrec;
  for (long i=tid;i<NR;i+=stride){
    float4 v=s3[i]; v.x=tf32r(v.x); v.y=tf32r(v.y); v.z=tf32r(v.z); v.w=tf32r(v.w); d3[i]=v;
  }
  const long NS = ((long)Bsz*Hh)/4;
  const float4* hs = (const float4*)h0; const float4* cs = (const float4*)c0;
  float4* gh = (float4*)g_h; float4* gc = (float4*)g_c; float4* gx = (float4*)g_x0;
  for (long i=tid;i<NS;i+=stride){
    float4 v0=hs[i];    v0.x=tf32r(v0.x); v0.y=tf32r(v0.y); v0.z=tf32r(v0.z); v0.w=tf32r(v0.w);
    float4 v1=hs[NS+i]; v1.x=tf32r(v1.x); v1.y=tf32r(v1.y); v1.z=tf32r(v1.z); v1.w=tf32r(v1.w);
    gh[1*NS + i] = v0;
    gh[3*NS + i] = v1;
    gc[i]      = cs[i];
    gc[NS + i] = cs[NS + i];
    gx[i] = make_float4(0.f,0.f,0.f,0.f);
  }
}

// ---- fused layer-step kernel: wmma tf32 GEMM (64x32xK) + LSTM cell / recons ----
// LSTM CTA: 8 hidden units x 4 gates = 32 gate cols, K = 4096 (concat x|h).
// Recons CTA: 32 output cols, K = 2048. Per-CTA staggered k-order.
__global__ void __launch_bounds__(256,2) lstm_kernel(
  const float* __restrict__ Ax, const float* __restrict__ Ah,
  const float* __restrict__ Wih, const float* __restrict__ Whh,
  const float* __restrict__ bih, const float* __restrict__ bhh,
  float* __restrict__ c_io, float* __restrict__ h_out,
  int n_lstm,
  const float* __restrict__ Arec, const float* __restrict__ Wrec,
  const float* __restrict__ brec, float* __restrict__ out_rec)
{
  extern __shared__ float smem[];
  const int tid = threadIdx.x;
  const bool is_rec = (int)blockIdx.x >= n_lstm;
  const int KT  = is_rec ? (Hh/BK) : (2*Hh/BK);        // 32 or 64
  const int j0  = is_rec ? 0 : (int)blockIdx.x*8;
  const int rn0 = is_rec ? ((int)blockIdx.x - n_lstm)*32 : 0;
  const int ks  = (int)blockIdx.x & (KT-1);            // stagger offset
  const float* A0 = is_rec ? Arec : Ax;

  // bias sums
  if (tid < 32){
    float bs;
    if (is_rec) bs = brec[rn0 + tid];
    else { int g = tid>>3, j = j0 + (tid&7); bs = bih[g*Hh + j] + bhh[g*Hh + j]; }
    smem[BSUM_OFF + tid] = bs;
  }

  const int aC = (tid & 15) << 2;
  const int aR0 = tid >> 4;
  const float* bw_lo[2]; const float* bw_hi[2];
  #pragma unroll
  for (int i=0;i<2;i++){
    int nn = aR0 + i*16;
    if (is_rec){ bw_lo[i] = Wrec + (long)(rn0+nn)*Hh; bw_hi[i] = bw_lo[i]; }
    else { long wr = (long)(nn>>3)*Hh + j0 + (nn&7); bw_lo[i] = Wih + wr*Hh; bw_hi[i] = Whh + wr*Hh; }
  }

  // load logical tile kt into stage s (physical tile = (kt+ks) mod KT)
  auto load_stage = [&](int s, int kt){
    int ktp = kt + ks; if (ktp >= KT) ktp -= KT;
    const int kb = ktp*BK + aC;
    float* stg = smem + s*STAGE_FLOATS;
    const bool lo = (is_rec || kb < Hh);
    #pragma unroll
    for (int i=0;i<4;i++){
      int r = aR0 + i*16;
      const float* src = lo ? (A0 + (long)r*Hh + kb) : (Ah + (long)r*Hh + kb - Hh);
      cpa16(saddr(&stg[r*LDA + aC]), src);
    }
    float* stgB = stg + A_STAGE_FLOATS;
    #pragma unroll
    for (int i=0;i<2;i++){
      int r = aR0 + i*16;
      const float* src = lo ? (bw_lo[i] + kb) : (bw_hi[i] + kb - Hh);
      cpa16(saddr(&stgB[r*LDA + aC]), src);
    }
    asm volatile("cp.async.commit_group;");
  };

  #pragma unroll
  for (int s=0; s<STAGES-1; ++s) load_stage(s, s);

  using FA = wmma::fragment<wmma::matrix_a,16,16,8,wmma::precision::tf32,wmma::row_major>;
  using FB = wmma::fragment<wmma::matrix_b,16,16,8,wmma::precision::tf32,wmma::col_major>;
  using FC = wmma::fragment<wmma::accumulator,16,16,8,float>;

  const int w  = tid>>5;
  const int wm = (w>>1)*16;        // 0,16,32,48
  const int wn = (w&1)*16;         // 0,16

  FC acc0, acc1;
  wmma::fill_fragment(acc0, 0.0f);
  wmma::fill_fragment(acc1, 0.0f);

  for (int kt=0; kt<KT; ++kt){
    asm volatile("cp.async.wait_group 2;");
    __syncthreads();
    const int nx = kt + (STAGES-1);
    if (nx < KT) load_stage(nx & (STAGES-1), nx);
    const float* stg = smem + (kt & (STAGES-1))*STAGE_FLOATS;
    const float* stgB = stg + A_STAGE_FLOATS;
    // software-pipelined fragments, dual accumulators (even/odd kk)
    FA a0, a1; FB b0, b1;
    wmma::load_matrix_sync(a0, &stg[wm*LDA + 0], LDA);
    wmma::load_matrix_sync(b0, &stgB[wn*LDA + 0], LDA);
    #pragma unroll
    for (int kk=0; kk<BK/8; ++kk){
      if (kk+1 < BK/8){
        if ((kk&1)==0){
          wmma::load_matrix_sync(a1, &stg[wm*LDA + (kk+1)*8], LDA);
          wmma::load_matrix_sync(b1, &stgB[wn*LDA + (kk+1)*8], LDA);
        } else {
          wmma::load_matrix_sync(a0, &stg[wm*LDA + (kk+1)*8], LDA);
          wmma::load_matrix_sync(b0, &stgB[wn*LDA + (kk+1)*8], LDA);
        }
      }
      if ((kk&1)==0) wmma::mma_sync(acc0, a0, b0, acc0);
      else           wmma::mma_sync(acc1, a1, b1, acc1);
    }
  }
  asm volatile("cp.async.wait_group 0;");
  __syncthreads();

  // combine dual accumulators, store, fused epilogue
  #pragma unroll
  for (int i=0; i<acc0.num_elements; ++i) acc0.x[i] += acc1.x[i];
  wmma::store_matrix_sync(&smem[wm*LDG + wn], acc0, LDG, wmma::mem_row_major);
  __syncthreads();

  const float* ep = smem;
  const float* bs = smem + BSUM_OFF;
  if (!is_rec){
    #pragma unroll
    for (int idx=tid; idx<Bsz*8; idx+=256){
      int b = idx>>3, jj = idx&7, j = j0+jj;
      float iv = ep[b*LDG + jj]      + bs[jj];
      float fv = ep[b*LDG + 8+jj]    + bs[8+jj];
      float gv = ep[b*LDG + 16+jj]   + bs[16+jj];
      float ov = ep[b*LDG + 24+jj]   + bs[24+jj];
      float co = c_io[(long)b*Hh + j];
      float cn = sigf(fv)*co + sigf(iv)*tanhf(gv);
      float hn = sigf(ov)*tanhf(cn);
      c_io[(long)b*Hh + j]  = cn;
      h_out[(long)b*Hh + j] = tf32r(hn);
    }
  } else {
    #pragma unroll
    for (int idx=tid; idx<Bsz*32; idx+=256){
      int b = idx>>5, nn = idx&31;
      out_rec[(long)b*INs + rn0 + nn] = ep[b*LDG+nn] + bs[nn];
    }
  }
}

extern "C" void kernel_launch(void* const* d_in, const int* in_sizes, int n_in,
                              void* d_out, int out_size)
{
  const float* h0  = (const float*)d_in[1];
  const float* c0  = (const float*)d_in[2];
  const float* Wih = (const float*)d_in[3];
  const float* Whh = (const float*)d_in[4];
  const float* bih = (const float*)d_in[5];
  const float* bhh = (const float*)d_in[6];
  const float* Wrec= (const float*)d_in[7];
  const float* brec= (const float*)d_in[8];
  float* out = (float*)d_out;

  void *p0,*p1,*p2,*p3,*p4,*p5;
  cudaGetSymbolAddress(&p0, g_Wih);
  cudaGetSymbolAddress(&p1, g_Whh);
  cudaGetSymbolAddress(&p2, g_Wrec);
  cudaGetSymbolAddress(&p3, g_h);
  cudaGetSymbolAddress(&p4, g_c);
  cudaGetSymbolAddress(&p5, g_x0);
  float* gWih = (float*)p0; float* gWhh = (float*)p1; float* gWrec = (float*)p2;
  float* gH   = (float*)p3; float* gC   = (float*)p4; float* gX0  = (float*)p5;

  cudaFuncSetAttribute(lstm_kernel, cudaFuncAttributeMaxDynamicSharedMemorySize, SMEM_BYTES);

  init_kernel<<<1024,256>>>(h0, c0, Wih, Whh, Wrec);

  const long NS = (long)Bsz*Hh;
  const long WOFF = (long)G4*Hh;

  for (int t=0; t<Tt; ++t){
    int rp = (t+1)&1, wp = t&1;
    float* h0r = gH + (0*2+rp)*NS;
    float* h0w = gH + (0*2+wp)*NS;
    float* h1r = gH + (1*2+rp)*NS;
    float* h1w = gH + (1*2+wp)*NS;
    const float* x = (t==0) ? gX0 : h1r;
    float* orow = (t==0) ? out : (out + (long)(Tt-t)*Bsz*INs);

    // layer 0 (+ fused recons of previous step's h1 when t>0)
    lstm_kernel<<<(t==0?NLSTM:NLSTM+NREC),256,SMEM_BYTES>>>(
      x, h0r, gWih, gWhh, bih, bhh, gC, h0w,
      NLSTM, x, gWrec, brec, orow);

    // layer 1
    lstm_kernel<<<NLSTM,256,SMEM_BYTES>>>(
      h0w, h1r, gWih + WOFF, gWhh + WOFF,
      bih + G4, bhh + G4, gC + NS, h1w,
      NLSTM, nullptr, gWrec, brec, nullptr);
  }

  // final recons of h1(127) -> output row 0
  lstm_kernel<<<NREC,256,SMEM_BYTES>>>(
    gX0, gX0, gWih, gWhh, bih, bhh, gC, gX0,
    0, gH + (1*2+1)*NS, gWrec, brec, out);
}